// round 17
// baseline (speedup 1.0000x reference)
#include <cuda_runtime.h>
#include <cuda_fp16.h>
#include <math.h>
#include <stdint.h>

// ---------------- problem constants ----------------
#define BB 4
#define TT 2048
#define DIM 1024
#define HH 16
#define NOPE 128
#define ROPE 64
#define VDIM 128
#define KVR 512
#define QKD 192            // NOPE + ROPE
#define MTOT (BB*TT)       // 8192
#define SCALE_F (0.07216878364870323f)  // 192^-0.5
#define NQCOL (HH*QKD)     // 3072
#define NKVA  (KVR+ROPE)   // 576

// ---------------- fp32 scratch ----------------
__device__ __align__(16) float g_KVA[(size_t)MTOT * NKVA];

// ---------------- fp16 planes ----------
__device__ __align__(16) __half g_xh   [(size_t)MTOT * DIM];
__device__ __align__(16) __half g_wqh  [(size_t)NQCOL * DIM];
__device__ __align__(16) __half g_wkvah[(size_t)NKVA * DIM];
__device__ __align__(16) __half g_wkvbh[(size_t)(HH*(NOPE+VDIM)) * KVR];
__device__ __align__(16) __half g_woh  [(size_t)DIM * (HH*VDIM)];
__device__ __align__(16) __half g_kvnh [(size_t)MTOT * KVR];
__device__ __align__(16) __half g_atth [(size_t)MTOT * HH * VDIM];

// ---------------- fp16 attention tensors ----------
__device__ __align__(16) __half g_qhl[(size_t)MTOT * HH * QKD];  // [b,h,t,192]
__device__ __align__(16) __half g_khl[(size_t)MTOT * HH * QKD];  // [b,h,t,192]
__device__ __align__(16) __half g_v16[(size_t)MTOT * HH * VDIM]; // [bt,h,128]
__device__ __align__(16) __half g_vhl[(size_t)MTOT * HH * VDIM]; // [b,h,d,t]

// ---------------- fused fp32 -> fp16 conversion of all inputs ----------------
#define N_X    ((size_t)MTOT * DIM)
#define N_WQ   ((size_t)NQCOL * DIM)
#define N_WKVA ((size_t)NKVA * DIM)
#define N_WKVB ((size_t)(HH*(NOPE+VDIM)) * KVR)
#define N_WO   ((size_t)DIM * (HH*VDIM))
#define N_CONV_TOTAL (N_X + N_WQ + N_WKVA + N_WKVB + N_WO)

__global__ void conv_all(const float* __restrict__ x, const float* __restrict__ wq,
                         const float* __restrict__ wkva, const float* __restrict__ wkvb,
                         const float* __restrict__ wo)
{
    size_t i = (size_t)blockIdx.x * blockDim.x + threadIdx.x;
    if (i >= N_CONV_TOTAL) return;
    if (i < N_X) {
        g_xh[i] = __float2half_rn(x[i]);
    } else if (i < N_X + N_WQ) {
        size_t j = i - N_X;
        g_wqh[j] = __float2half_rn(wq[j]);
    } else if (i < N_X + N_WQ + N_WKVA) {
        size_t j = i - N_X - N_WQ;
        g_wkvah[j] = __float2half_rn(wkva[j]);
    } else if (i < N_X + N_WQ + N_WKVA + N_WKVB) {
        size_t j = i - N_X - N_WQ - N_WKVA;
        g_wkvbh[j] = __float2half_rn(wkvb[j]);
    } else {
        size_t j = i - N_X - N_WQ - N_WKVA - N_WKVB;
        g_woh[j] = __float2half_rn(wo[j]);
    }
}

// ---------------- HMMA helpers ----------------
__device__ __forceinline__ void ldsm4(uint32_t* r, uint32_t addr) {
    asm volatile("ldmatrix.sync.aligned.m8n8.x4.shared.b16 {%0,%1,%2,%3},[%4];"
                 : "=r"(r[0]), "=r"(r[1]), "=r"(r[2]), "=r"(r[3]) : "r"(addr));
}
__device__ __forceinline__ void mma16816(float* c, const uint32_t* a, const uint32_t* b) {
    asm volatile(
        "mma.sync.aligned.m16n8k16.row.col.f32.f16.f16.f32 "
        "{%0,%1,%2,%3},{%4,%5,%6,%7},{%8,%9},{%0,%1,%2,%3};"
        : "+f"(c[0]), "+f"(c[1]), "+f"(c[2]), "+f"(c[3])
        : "r"(a[0]), "r"(a[1]), "r"(a[2]), "r"(a[3]), "r"(b[0]), "r"(b[1]));
}
__device__ __forceinline__ void mma16816b(float* c, const uint32_t* a, uint32_t b0, uint32_t b1) {
    asm volatile(
        "mma.sync.aligned.m16n8k16.row.col.f32.f16.f16.f32 "
        "{%0,%1,%2,%3},{%4,%5,%6,%7},{%8,%9},{%0,%1,%2,%3};"
        : "+f"(c[0]), "+f"(c[1]), "+f"(c[2]), "+f"(c[3])
        : "r"(a[0]), "r"(a[1]), "r"(a[2]), "r"(a[3]), "r"(b0), "r"(b1));
}
__device__ __forceinline__ uint32_t pack_h2(__half a, __half b) {
    __half2 t; t.x = a; t.y = b;
    return *(uint32_t*)&t;
}
__device__ __forceinline__ uint32_t smem_u32(const void* p) {
    uint32_t a;
    asm("{ .reg .u64 t; cvta.to.shared.u64 t, %1; cvt.u32.u64 %0, t; }" : "=r"(a) : "l"(p));
    return a;
}
__device__ __forceinline__ void cp16(uint32_t d, const void* s) {
    asm volatile("cp.async.cg.shared.global [%0],[%1],16;" :: "r"(d), "l"(s));
}
__device__ __forceinline__ void cp16z(uint32_t d, const void* s, unsigned sz) {
    asm volatile("cp.async.cg.shared.global [%0],[%1],16,%2;" :: "r"(d), "l"(s), "r"(sz));
}
__device__ __forceinline__ void cp_commit() { asm volatile("cp.async.commit_group;"); }
template <int N>
__device__ __forceinline__ void cp_wait() {
    asm volatile("cp.async.wait_group %0;" :: "n"(N) : "memory");
}

// ---------------- HMMA GEMM (cp.async 2-stage, fp16): C = A@B^T + bias ----
// MODE 0: fp32 C. MODE 2: kv split -> g_khl/g_v16. MODE 3: merged q(rope)+kva.
#define LDPAD 40
#define G_PLANE_B (128 * LDPAD * 2)
#define G_STAGE_B (2 * G_PLANE_B)
#define G_SMEM_B  (2 * G_STAGE_B)   // 40960

template<int MODE>
__global__ __launch_bounds__(256, 2) void gemm_hmma(
    const __half* __restrict__ A,
    const __half* __restrict__ B,
    const __half* __restrict__ B2,
    const float* __restrict__ bias, const float* __restrict__ bias2,
    float* __restrict__ C,
    int M, int N, int K,
    const float* __restrict__ cosv, const float* __restrict__ sinv)
{
    extern __shared__ char smraw[];
    const uint32_t sbase = smem_u32(smraw);

    const int tid  = threadIdx.x;
    const int lane = tid & 31;
    const int wid  = tid >> 5;
    const int brow = blockIdx.y * 128;
    const int bcol = blockIdx.x * 128;

    const int lc = tid & 3;
    const int lr = tid >> 2;

    const int wm = (wid & 3) * 32;
    const int wn = (wid >> 2) * 64;

    float acc[2][8][4];
#pragma unroll
    for (int mi = 0; mi < 2; mi++)
#pragma unroll
        for (int ni = 0; ni < 8; ni++)
#pragma unroll
            for (int e = 0; e < 4; e++) acc[mi][ni][e] = 0.f;

    const uint32_t rowoff0 = (uint32_t)(lr * LDPAD + lc * 8) * 2;
    const uint32_t rowoff1 = (uint32_t)((lr + 64) * LDPAD + lc * 8) * 2;

    const int arow0 = brow + lr, arow1 = brow + lr + 64;
    const int ncol0 = bcol + lr, ncol1 = bcol + lr + 64;

    // B-row pointer resolution (MODE 3: rows >= NQCOL come from B2)
    const __half *bp0, *bp1;
    unsigned bz0, bz1;
    if (MODE == 3) {
        if (ncol0 < NQCOL) { bp0 = B + (size_t)ncol0 * K; bz0 = 16u; }
        else { int rr = ncol0 - NQCOL; bp0 = B2 + (size_t)(rr < NKVA ? rr : 0) * K; bz0 = rr < NKVA ? 16u : 0u; }
        if (ncol1 < NQCOL) { bp1 = B + (size_t)ncol1 * K; bz1 = 16u; }
        else { int rr = ncol1 - NQCOL; bp1 = B2 + (size_t)(rr < NKVA ? rr : 0) * K; bz1 = rr < NKVA ? 16u : 0u; }
    } else {
        int nc0 = ncol0 < N ? ncol0 : 0;
        int nc1 = ncol1 < N ? ncol1 : 0;
        bp0 = B + (size_t)nc0 * K; bz0 = ncol0 < N ? 16u : 0u;
        bp1 = B + (size_t)nc1 * K; bz1 = ncol1 < N ? 16u : 0u;
    }

    const int nch = K / 32;

    auto stage_load = [&](int c, int s) {
        const int kk = c * 32 + lc * 8;
        const uint32_t as = sbase + (uint32_t)s * G_STAGE_B;
        const uint32_t bs = as + G_PLANE_B;
        cp16(as + rowoff0, A + (size_t)arow0 * K + kk);
        cp16(as + rowoff1, A + (size_t)arow1 * K + kk);
        cp16z(bs + rowoff0, bp0 + kk, bz0);
        cp16z(bs + rowoff1, bp1 + kk, bz1);
        cp_commit();
    };

    stage_load(0, 0);
    if (nch > 1) stage_load(1, 1);

    for (int c = 0; c < nch; c++) {
        const int s = c & 1;
        cp_wait<1>();
        __syncthreads();

        const uint32_t aS = sbase + (uint32_t)s * G_STAGE_B;
        const uint32_t bS = aS + G_PLANE_B;

#pragma unroll
        for (int ks = 0; ks < 2; ks++) {
            const int kc = ks * 16;
            uint32_t a_h[2][4];
#pragma unroll
            for (int mi = 0; mi < 2; mi++) {
                uint32_t addr = aS + ((wm + mi*16 + (lane & 15)) * LDPAD + kc + (lane >> 4) * 8) * 2;
                ldsm4(a_h[mi], addr);
            }
            uint32_t b_h[4][4];
#pragma unroll
            for (int np = 0; np < 4; np++) {
                uint32_t baddr = bS + ((wn + np*16 + (lane & 15)) * LDPAD + kc + (lane >> 4) * 8) * 2;
                ldsm4(b_h[np], baddr);
            }
#pragma unroll
            for (int np = 0; np < 4; np++) {
#pragma unroll
                for (int hf = 0; hf < 2; hf++) {
                    const int ni = np*2 + hf;
#pragma unroll
                    for (int mi = 0; mi < 2; mi++) {
                        mma16816b(acc[mi][ni], a_h[mi], b_h[np][hf], b_h[np][hf+2]);
                    }
                }
            }
        }
        __syncthreads();
        if (c + 2 < nch) stage_load(c + 2, s);
    }

    // ---------------- epilogues ----------------
#pragma unroll
    for (int mi = 0; mi < 2; mi++) {
        int r0 = brow + wm + mi*16 + (lane >> 2);
        int bq = r0 >> 11;          // batch
        int tq = r0 & (TT - 1);     // time (rows r0 and r0+8 same batch)
#pragma unroll
        for (int ni = 0; ni < 8; ni++) {
            int c0 = bcol + wn + ni*8 + (lane & 3) * 2;
            if (MODE == 0) {
                if (c0 < N) {
                    float b0 = bias[c0], b1 = bias[c0+1];
                    C[(size_t)r0 * N + c0]       = acc[mi][ni][0] + b0;
                    C[(size_t)r0 * N + c0 + 1]   = acc[mi][ni][1] + b1;
                    C[(size_t)(r0+8) * N + c0]   = acc[mi][ni][2] + b0;
                    C[(size_t)(r0+8) * N + c0+1] = acc[mi][ni][3] + b1;
                }
            } else if (MODE == 3) {
                if (c0 < NQCOL) {
                    // q: rope + scale, write fp16 [b,h,t,192]
                    int h = c0 / QKD;
                    int d = c0 - h * QKD;
                    float b0 = bias[c0], b1 = bias[c0+1];
                    float v0 = acc[mi][ni][0] + b0, v1 = acc[mi][ni][1] + b1; // row r0
                    float w0 = acc[mi][ni][2] + b0, w1 = acc[mi][ni][3] + b1; // row r0+8
                    if (d < NOPE) {
                        v0 *= SCALE_F; v1 *= SCALE_F; w0 *= SCALE_F; w1 *= SCALE_F;
                    } else {
                        int pi = (d - NOPE) >> 1;
                        float ca = cosv[tq*32 + pi],     sa = sinv[tq*32 + pi];
                        float cb = cosv[(tq+8)*32 + pi], sb = sinv[(tq+8)*32 + pi];
                        float t0 = (v0*ca - v1*sa) * SCALE_F;
                        float t1 = (v0*sa + v1*ca) * SCALE_F;
                        v0 = t0; v1 = t1;
                        t0 = (w0*cb - w1*sb) * SCALE_F;
                        t1 = (w0*sb + w1*cb) * SCALE_F;
                        w0 = t0; w1 = t1;
                    }
                    size_t base = (((size_t)bq*HH + h)*TT + tq)*QKD + d;
                    *(__half2*)&g_qhl[base]           = __floats2half2_rn(v0, v1);
                    *(__half2*)&g_qhl[base + 8*QKD]   = __floats2half2_rn(w0, w1);
                } else {
                    int col = c0 - NQCOL;
                    if (col < NKVA) {
                        float b0 = bias2[col], b1 = bias2[col+1];
                        g_KVA[(size_t)r0 * NKVA + col]         = acc[mi][ni][0] + b0;
                        g_KVA[(size_t)r0 * NKVA + col + 1]     = acc[mi][ni][1] + b1;
                        g_KVA[(size_t)(r0+8) * NKVA + col]     = acc[mi][ni][2] + b0;
                        g_KVA[(size_t)(r0+8) * NKVA + col + 1] = acc[mi][ni][3] + b1;
                    }
                }
            } else {
                // MODE 2 kv: split k_nope -> g_khl [b,h,t,192], v -> g_v16 [bt,h,128]
                int h  = c0 >> 8;
                int dd = c0 & 255;
                float b0 = bias[c0], b1 = bias[c0+1];
                float v0 = acc[mi][ni][0] + b0, v1 = acc[mi][ni][1] + b1;
                float w0 = acc[mi][ni][2] + b0, w1 = acc[mi][ni][3] + b1;
                if (dd < NOPE) {
                    size_t base = (((size_t)bq*HH + h)*TT + tq)*QKD + dd;
                    *(__half2*)&g_khl[base]         = __floats2half2_rn(v0, v1);
                    *(__half2*)&g_khl[base + 8*QKD] = __floats2half2_rn(w0, w1);
                } else {
                    size_t base = ((size_t)r0*HH + h)*VDIM + (dd - NOPE);
                    *(__half2*)&g_v16[base]               = __floats2half2_rn(v0, v1);
                    *(__half2*)&g_v16[base + 8*HH*VDIM]   = __floats2half2_rn(w0, w1);
                }
            }
        }
    }
}

// ---------------- kv_a post: rms_norm -> g_kvnh (fp16), k_rope -> g_khl (all heads) ----
__global__ __launch_bounds__(128) void kva_post_kernel(const float* __restrict__ cosv,
                                                       const float* __restrict__ sinv)
{
    __shared__ float red[4];
    __shared__ float kr[64];
    const int bt = blockIdx.x;
    const int b  = bt >> 11;
    const int t  = bt & (TT - 1);
    const float* a = g_KVA + (size_t)bt * NKVA;
    const int tid = threadIdx.x;

    float ss = 0.f;
    for (int d = tid; d < KVR; d += 128) { float v = a[d]; ss += v * v; }
#pragma unroll
    for (int off = 16; off; off >>= 1) ss += __shfl_xor_sync(0xffffffffu, ss, off);
    if ((tid & 31) == 0) red[tid >> 5] = ss;

    if (tid < 32) {
        int i = tid;
        float c = cosv[t*32 + i];
        float s = sinv[t*32 + i];
        float xr = a[KVR + 2*i];
        float xi = a[KVR + 2*i + 1];
        kr[2*i]     = xr*c - xi*s;
        kr[2*i + 1] = xr*s + xi*c;
    }
    __syncthreads();
    float total = red[0] + red[1] + red[2] + red[3];
    float r = rsqrtf(total * (1.0f / KVR) + 1e-6f);

    __half* o = g_kvnh + (size_t)bt * KVR;
    for (int d = tid; d < KVR; d += 128) o[d] = __float2half_rn(a[d] * r);

    for (int idx = tid; idx < HH * ROPE; idx += 128) {
        int h  = idx >> 6;
        int i2 = idx & 63;
        g_khl[(((size_t)b*HH + h)*TT + t)*QKD + NOPE + i2] = __float2half_rn(kr[i2]);
    }
}

// ---------------- build V transposed [b,h,d,t] from fp16 g_v16 ----------------
__global__ void build_v_hl()
{
    __shared__ unsigned short tile[32][34];
    const int bh = blockIdx.z;
    const int b = bh / HH, h = bh % HH;
    const int t0 = blockIdx.x * 32;
    const int d0 = blockIdx.y * 32;
    const int tx = threadIdx.x, ty = threadIdx.y;

#pragma unroll
    for (int k = 0; k < 4; k++) {
        int t = t0 + ty + k*8;
        tile[ty + k*8][tx] =
            *(const unsigned short*)&g_v16[((size_t)(b*TT + t)*HH + h)*VDIM + d0 + tx];
    }
    __syncthreads();
#pragma unroll
    for (int k = 0; k < 4; k++) {
        int d = d0 + ty + k*8;
        *(unsigned short*)&g_vhl[((size_t)bh*VDIM + d)*TT + t0 + tx] = tile[tx][ty + k*8];
    }
}

// ---------------- HMMA flash attention (fp16, double-buffered, balanced 2-phase) --
#define QS_STRIDE 200
#define VS_STRIDE 72
#define SM_Q_ELEMS (128*QS_STRIDE)
#define SM_K_ELEMS (64*QS_STRIDE)
#define SM_V_ELEMS (128*VS_STRIDE)
#define KV_STAGE_ELEMS (SM_K_ELEMS + SM_V_ELEMS)
#define ATT_SMEM_B ((SM_Q_ELEMS + 2*KV_STAGE_ELEMS) * 2)

__global__ __launch_bounds__(256, 1) void attn_hmma()
{
    extern __shared__ __half smb[];
    __half* qs = smb;

    const int b = blockIdx.z, h = blockIdx.y;
    const int tid = threadIdx.x, lane = tid & 31, w = tid >> 5;
    const size_t bh = (size_t)b * HH + h;

    const int g  = lane >> 2;
    const int qc = (lane & 3) * 2;

    const uint32_t sQ  = smem_u32(qs);
    const uint32_t sKV = sQ + SM_Q_ELEMS * 2;

    // two phases: query blocks bx and 15-bx (total work uniform = 36 tiles)
#pragma unroll 1
    for (int ph = 0; ph < 2; ph++) {
        const int qb = ph == 0 ? blockIdx.x : (15 - blockIdx.x);
        const int qbase = qb * 128;
        const int qr0 = qbase + w*16 + g;

        __syncthreads();
        {
            const __half* qg = g_qhl + (bh*TT + qbase)*QKD;
            for (int i = tid; i < 128*24; i += 256) {
                int r = i / 24, c = i % 24;
                *(uint4*)&qs[r*QS_STRIDE + c*8] = *(const uint4*)&qg[(size_t)r*QKD + c*8];
            }
        }
        __syncthreads();

        float m0 = -1e30f, m1 = -1e30f, l0 = 0.f, l1 = 0.f;
        float o[16][4];
#pragma unroll
        for (int nv = 0; nv < 16; nv++)
#pragma unroll
            for (int e = 0; e < 4; e++) o[nv][e] = 0.f;

        const int ntiles = qb + 2;   // (qbase/64 + 2) where qbase = qb*128 -> 2*qb+2... 

        // NOTE: qbase/64 = qb*2, so tiles covering keys [0, qbase+127] is qb*2+2
        const int ntiles2 = qb*2 + 2;
        (void)ntiles;

        auto stage = [&](int kb) {
            const int s = kb & 1;
            const uint32_t ksb = sKV + (uint32_t)s * KV_STAGE_ELEMS * 2;
            const uint32_t vsb = ksb + SM_K_ELEMS * 2;
            const __half* kg = g_khl + (bh*TT + kb*64)*QKD;
            const __half* vg = g_vhl + bh*VDIM*TT + kb*64;
            for (int i = tid; i < 64*24; i += 256) {
                int r = i / 24, c = i % 24;
                cp16(ksb + (r*QS_STRIDE + c*8)*2, kg + (size_t)r*QKD + c*8);
            }
            for (int i = tid; i < 128*8; i += 256) {
                int d = i / 8, c = i % 8;
                cp16(vsb + (d*VS_STRIDE + c*8)*2, vg + (size_t)d*TT + c*8);
            }
            cp_commit();
        };

        stage(0);

        for (int kb = 0; kb < ntiles2; kb++) {
            const int kbase = kb * 64;
            if (kb + 1 < ntiles2) { stage(kb + 1); cp_wait<1>(); }
            else                  { cp_wait<0>(); }
            __syncthreads();

            const uint32_t sK = sKV + (uint32_t)(kb & 1) * KV_STAGE_ELEMS * 2;
            const uint32_t sV = sK + SM_K_ELEMS * 2;

            float s[8][4];
#pragma unroll
            for (int ni = 0; ni < 8; ni++)
#pragma unroll
                for (int e = 0; e < 4; e++) s[ni][e] = 0.f;

#pragma unroll
            for (int kp = 0; kp < 6; kp++) {
                uint32_t ah0[4], ah1[4];
                uint32_t ab = sQ + ((w*16 + (lane & 15))*QS_STRIDE + kp*32 + (lane >> 4)*8) * 2;
                ldsm4(ah0, ab);
                ldsm4(ah1, ab + 32);
#pragma unroll
                for (int ni = 0; ni < 8; ni++) {
                    uint32_t bb = sK + ((ni*8 + (lane & 7))*QS_STRIDE + kp*32 + (lane >> 3)*8) * 2;
                    uint32_t bh4[4];
                    ldsm4(bh4, bb);
                    mma16816(s[ni], ah0, bh4);
                    mma16816(s[ni], ah1, bh4 + 2);
                }
            }

            if (kbase + 63 > qr0) {
#pragma unroll
                for (int ni = 0; ni < 8; ni++) {
                    int col = kbase + ni*8 + qc;
                    if (col     > qr0)     s[ni][0] = -1e30f;
                    if (col + 1 > qr0)     s[ni][1] = -1e30f;
                    if (col     > qr0 + 8) s[ni][2] = -1e30f;
                    if (col + 1 > qr0 + 8) s[ni][3] = -1e30f;
                }
            }

            float rm0 = -1e30f, rm1 = -1e30f;
#pragma unroll
            for (int ni = 0; ni < 8; ni++) {
                rm0 = fmaxf(rm0, fmaxf(s[ni][0], s[ni][1]));
                rm1 = fmaxf(rm1, fmaxf(s[ni][2], s[ni][3]));
            }
            rm0 = fmaxf(rm0, __shfl_xor_sync(0xffffffffu, rm0, 1));
            rm0 = fmaxf(rm0, __shfl_xor_sync(0xffffffffu, rm0, 2));
            rm1 = fmaxf(rm1, __shfl_xor_sync(0xffffffffu, rm1, 1));
            rm1 = fmaxf(rm1, __shfl_xor_sync(0xffffffffu, rm1, 2));
            float nm0 = fmaxf(m0, rm0), nm1 = fmaxf(m1, rm1);
            float c0 = __expf(m0 - nm0), c1 = __expf(m1 - nm1);

            float rs0 = 0.f, rs1 = 0.f;
#pragma unroll
            for (int ni = 0; ni < 8; ni++) {
                s[ni][0] = __expf(s[ni][0] - nm0); rs0 += s[ni][0];
                s[ni][1] = __expf(s[ni][1] - nm0); rs0 += s[ni][1];
                s[ni][2] = __expf(s[ni][2] - nm1); rs1 += s[ni][2];
                s[ni][3] = __expf(s[ni][3] - nm1); rs1 += s[ni][3];
            }
            rs0 += __shfl_xor_sync(0xffffffffu, rs0, 1);
            rs0 += __shfl_xor_sync(0xffffffffu, rs0, 2);
            rs1 += __shfl_xor_sync(0xffffffffu, rs1, 1);
            rs1 += __shfl_xor_sync(0xffffffffu, rs1, 2);
            l0 = l0 * c0 + rs0;
            l1 = l1 * c1 + rs1;
            m0 = nm0; m1 = nm1;
#pragma unroll
            for (int nv = 0; nv < 16; nv++) {
                o[nv][0] *= c0; o[nv][1] *= c0;
                o[nv][2] *= c1; o[nv][3] *= c1;
            }

#pragma unroll
            for (int kp = 0; kp < 2; kp++) {
                uint32_t ph2[2][4];
#pragma unroll
                for (int ss2 = 0; ss2 < 2; ss2++) {
                    int n0 = kp*4 + ss2*2;
#pragma unroll
                    for (int half = 0; half < 2; half++) {
                        int nt = n0 + half;
                        ph2[ss2][half*2 + 0] = pack_h2(__float2half_rn(s[nt][0]), __float2half_rn(s[nt][1]));
                        ph2[ss2][half*2 + 1] = pack_h2(__float2half_rn(s[nt][2]), __float2half_rn(s[nt][3]));
                    }
                }
#pragma unroll
                for (int nv = 0; nv < 16; nv++) {
                    uint32_t vb = sV + ((nv*8 + (lane & 7))*VS_STRIDE + kp*32 + (lane >> 3)*8) * 2;
                    uint32_t vh4[4];
                    ldsm4(vh4, vb);
                    mma16816(o[nv], ph2[0], vh4);
                    mma16816(o[nv], ph2[1], vh4 + 2);
                }
            }
            __syncthreads();
        }

        // epilogue: write g_atth fp16 directly
        float inv0 = 1.f / l0, inv1 = 1.f / l1;
        __half* op0 = g_atth + (size_t)(b*TT + qr0) * (HH*VDIM) + h*VDIM;
        __half* op1 = op0 + (size_t)8 * (HH*VDIM);
#pragma unroll
        for (int nv = 0; nv < 16; nv++) {
            int d = nv*8 + qc;
            op0[d]     = __float2half_rn(o[nv][0] * inv0);
            op0[d + 1] = __float2half_rn(o[nv][1] * inv0);
            op1[d]     = __float2half_rn(o[nv][2] * inv1);
            op1[d + 1] = __float2half_rn(o[nv][3] * inv1);
        }
    }
}

// ---------------- launch ----------------
extern "C" void kernel_launch(void* const* d_in, const int* in_sizes, int n_in,
                              void* d_out, int out_size)
{
    const float* x       = (const float*)d_in[0];
    const float* wq_w    = (const float*)d_in[1];
    const float* wq_b    = (const float*)d_in[2];
    const float* wkv_a_w = (const float*)d_in[3];
    const float* wkv_a_b = (const float*)d_in[4];
    const float* wkv_b_w = (const float*)d_in[5];
    const float* wkv_b_b = (const float*)d_in[6];
    const float* wo_w    = (const float*)d_in[7];
    const float* wo_b    = (const float*)d_in[8];
    const float* cosv    = (const float*)d_in[9];
    const float* sinv    = (const float*)d_in[10];
    float* out = (float*)d_out;

    __half *xh, *wqh, *wkvah, *wkvbh, *woh, *kvnh, *atth;
    cudaGetSymbolAddress((void**)&xh,    g_xh);
    cudaGetSymbolAddress((void**)&wqh,   g_wqh);
    cudaGetSymbolAddress((void**)&wkvah, g_wkvah);
    cudaGetSymbolAddress((void**)&wkvbh, g_wkvbh);
    cudaGetSymbolAddress((void**)&woh,   g_woh);
    cudaGetSymbolAddress((void**)&kvnh,  g_kvnh);
    cudaGetSymbolAddress((void**)&atth,  g_atth);

    const size_t nATT = (size_t)MTOT * HH * VDIM;

    cudaFuncSetAttribute(gemm_hmma<0>, cudaFuncAttributeMaxDynamicSharedMemorySize, G_SMEM_B);
    cudaFuncSetAttribute(gemm_hmma<2>, cudaFuncAttributeMaxDynamicSharedMemorySize, G_SMEM_B);
    cudaFuncSetAttribute(gemm_hmma<3>, cudaFuncAttributeMaxDynamicSharedMemorySize, G_SMEM_B);

    // 0) all fp32->fp16 conversions in one launch
    conv_all<<<(unsigned)((N_CONV_TOTAL + 255) / 256), 256>>>(x, wq_w, wkv_a_w, wkv_b_w, wo_w);

    // 1) merged: q = x@wq^T+b (rope+scale -> g_qhl) AND kv_a = x@wkva^T+b (-> g_KVA)
    //    N logical = 3072 + 576 = 3648, grid x = ceil(3648/128) = 29
    gemm_hmma<3><<<dim3(29, MTOT/128), 256, G_SMEM_B>>>(
        xh, wqh, wkvah, wq_b, wkv_a_b, nullptr, MTOT, NQCOL + NKVA, DIM, cosv, sinv);
    // 2) rms norm (-> g_kvnh fp16) + k rope (-> g_khl rope section, all heads)
    kva_post_kernel<<<MTOT, 128>>>(cosv, sinv);
    // 3) kv = norm @ wkv_b^T + b  (split fused: k_nope -> g_khl, v -> g_v16)
    gemm_hmma<2><<<dim3(HH*(NOPE+VDIM)/128, MTOT/128), 256, G_SMEM_B>>>(
        kvnh, wkvbh, nullptr, wkv_b_b, nullptr, nullptr, MTOT, HH*(NOPE+VDIM), KVR, nullptr, nullptr);
    // 4) transpose V -> g_vhl [b,h,d,t]
    build_v_hl<<<dim3(TT/32, VDIM/32, BB*HH), dim3(32, 8)>>>();
    // 5) flash attention (balanced 2-phase, double-buffered staging) -> g_atth
    cudaFuncSetAttribute(attn_hmma, cudaFuncAttributeMaxDynamicSharedMemorySize, ATT_SMEM_B);
    attn_hmma<<<dim3(8, HH, BB), 256, ATT_SMEM_B>>>();
    // 6) out = att @ wo^T + b
    gemm_hmma<0><<<dim3(DIM/128, MTOT/128), 256, G_SMEM_B>>>(
        atth, woh, nullptr, wo_b, nullptr, out, MTOT, DIM, HH*VDIM, nullptr, nullptr);
}